// round 5
// baseline (speedup 1.0000x reference)
#include <cuda_runtime.h>
#include <cuda_bf16.h>

#define N_NODES   100000
#define N_EDGES   1600000
#define D         128
#define N_GRAPHS  512
#define N_CLASSES 4
#define SCAN_BS   1024
#define SCAN_NBLK ((N_NODES + SCAN_BS - 1) / SCAN_BS)   // 98

// ---------------- scratch (device globals; 16B aligned for LDG/STG.128) ----
__device__ __align__(16) float g_agg[N_NODES * D];
__device__ __align__(16) float g_h1 [N_NODES * D];
__device__ __align__(16) float g_h2 [N_NODES * D];
__device__ int g_deg   [N_NODES];
__device__ int g_incl  [N_NODES];
__device__ int g_rowptr[N_NODES + 1];
__device__ int g_cursor[N_NODES];
__device__ int g_csr   [N_EDGES];
__device__ int g_bsum  [SCAN_NBLK];
__device__ int g_boff  [SCAN_NBLK];
__device__ int g_is64;   // 1 if index tensors are int64, 0 if int32

// ---------------- dtype detection ----------------
// If edge data is int64, each u64 word is a node id < N_NODES (hi bits 0).
// If int32, words pack two ids -> almost surely >= 2^32.
__global__ void detect_kernel(const void* ei) {
    if (threadIdx.x == 0 && blockIdx.x == 0) {
        const unsigned long long* p = (const unsigned long long*)ei;
        int ok64 = 1;
        for (int i = 0; i < 16; i++)
            if (p[i] >= (unsigned long long)N_NODES) { ok64 = 0; break; }
        g_is64 = ok64;
    }
}

// Flag-branching index load: element i of a flat index buffer.
__device__ __forceinline__ int load_idx(const void* base, long long i) {
    return g_is64 ? (int)((const long long*)base)[i]
                  : ((const int*)base)[i];
}

// ---------------- CSR build ----------------
__global__ void zero_int_kernel(int* __restrict__ p, int n) {
    int i = blockIdx.x * blockDim.x + threadIdx.x;
    int stride = gridDim.x * blockDim.x;
    for (; i < n; i += stride) p[i] = 0;
}

__global__ void deg_kernel(const void* __restrict__ ei, int* __restrict__ deg, int ne) {
    int i = blockIdx.x * blockDim.x + threadIdx.x;
    int stride = gridDim.x * blockDim.x;
    for (; i < ne; i += stride) {
        int d = load_idx(ei, (long long)N_EDGES + i);   // dst row
        if ((unsigned)d < (unsigned)N_NODES)
            atomicAdd(&deg[d], 1);
    }
}

__global__ void scan1_kernel(const int* __restrict__ deg, int* __restrict__ incl,
                             int* __restrict__ bsum, int n) {
    __shared__ int s[SCAN_BS];
    int i = blockIdx.x * SCAN_BS + threadIdx.x;
    int v = (i < n) ? deg[i] : 0;
    s[threadIdx.x] = v;
    __syncthreads();
    for (int off = 1; off < SCAN_BS; off <<= 1) {
        int t = (threadIdx.x >= off) ? s[threadIdx.x - off] : 0;
        __syncthreads();
        s[threadIdx.x] += t;
        __syncthreads();
    }
    if (i < n) incl[i] = s[threadIdx.x];
    if (threadIdx.x == SCAN_BS - 1) bsum[blockIdx.x] = s[SCAN_BS - 1];
}

__global__ void scan2_kernel(const int* __restrict__ bsum, int* __restrict__ boff) {
    if (threadIdx.x == 0) {
        int running = 0;
        for (int b = 0; b < SCAN_NBLK; b++) { boff[b] = running; running += bsum[b]; }
    }
}

__global__ void scan3_kernel(const int* __restrict__ incl, const int* __restrict__ deg,
                             const int* __restrict__ boff, int* __restrict__ rowptr,
                             int* __restrict__ cursor, int n, int total) {
    int i = blockIdx.x * SCAN_BS + threadIdx.x;
    if (i < n) {
        int ex = incl[i] - deg[i] + boff[blockIdx.x];
        rowptr[i] = ex;
        cursor[i] = ex;
        if (i == n - 1) rowptr[n] = total;
    }
}

__global__ void fill_kernel(const void* __restrict__ ei,
                            int* __restrict__ cursor, int* __restrict__ csr, int ne) {
    int i = blockIdx.x * blockDim.x + threadIdx.x;
    int stride = gridDim.x * blockDim.x;
    for (; i < ne; i += stride) {
        int s = load_idx(ei, i);                       // src row
        int d = load_idx(ei, (long long)N_EDGES + i);  // dst row
        if ((unsigned)d < (unsigned)N_NODES && (unsigned)s < (unsigned)N_NODES) {
            int pos = atomicAdd(&cursor[d], 1);
            if ((unsigned)pos < (unsigned)N_EDGES) csr[pos] = s;
        }
    }
}

// ---------------- gather aggregate: agg[n] = mean_{e: dst=n} feat[src_e] ----
__global__ void gather_kernel(const float4* __restrict__ feat4,
                              const int* __restrict__ rowptr,
                              const int* __restrict__ csr,
                              float4* __restrict__ agg4, int n) {
    int w    = (blockIdx.x * blockDim.x + threadIdx.x) >> 5;
    int lane = threadIdx.x & 31;
    if (w >= n) return;
    int beg = rowptr[w], end = rowptr[w + 1];
    float4 acc = make_float4(0.f, 0.f, 0.f, 0.f);
    for (int e = beg; e < end; e++) {
        int s = __ldg(&csr[e]);
        float4 v = feat4[(long long)s * 32 + lane];
        acc.x += v.x; acc.y += v.y; acc.z += v.z; acc.w += v.w;
    }
    float inv = 1.0f / fmaxf((float)(end - beg), 1.0f);
    acc.x *= inv; acc.y *= inv; acc.z *= inv; acc.w *= inv;
    agg4[(long long)w * 32 + lane] = acc;
}

// ---------------- fused SAGE layer GEMM ------------------------------------
// out[r, :] = relu( agg[r,:] @ Wl^T + x[r,:] @ Wr^T + b )   (agg pre-scaled)
#define SI 132
__global__ __launch_bounds__(256)
void gemm_fused_kernel(const float* __restrict__ agg,
                       const float* __restrict__ xin,
                       const float* __restrict__ Wl,
                       const float* __restrict__ Wr,
                       const float* __restrict__ bias,
                       float* __restrict__ out, int nrows) {
    extern __shared__ float sm[];
    float* sIn = sm;             // [128][SI]
    float* sWt = sm + 128 * SI;  // [128][SI]  weights transposed [k][c]

    const int tid  = threadIdx.x;
    const int row0 = blockIdx.x * 128;
    const int ty = tid >> 4, tx = tid & 15;
    const int r0 = ty * 8, c0 = tx * 8;

    float acc[8][8];
#pragma unroll
    for (int i = 0; i < 8; i++)
#pragma unroll
        for (int j = 0; j < 8; j++) acc[i][j] = 0.0f;

#pragma unroll 1
    for (int chunk = 0; chunk < 2; ++chunk) {
        const float* In = chunk ? xin : agg;
        const float* W  = chunk ? Wr  : Wl;

        for (int idx = tid; idx < 128 * (D / 4); idx += 256) {
            int r  = idx >> 5;
            int k4 = (idx & 31) * 4;
            int grow = row0 + r;
            float4 v = make_float4(0.f, 0.f, 0.f, 0.f);
            if (grow < nrows)
                v = *reinterpret_cast<const float4*>(&In[(long long)grow * D + k4]);
            *reinterpret_cast<float4*>(&sIn[r * SI + k4]) = v;
        }
        for (int idx = tid; idx < D * D; idx += 256) {
            int c = idx >> 7, k = idx & 127;
            sWt[k * SI + c] = W[idx];
        }
        __syncthreads();

#pragma unroll 4
        for (int k4 = 0; k4 < D; k4 += 4) {
            float4 a[8];
#pragma unroll
            for (int i = 0; i < 8; i++)
                a[i] = *reinterpret_cast<const float4*>(&sIn[(r0 + i) * SI + k4]);
#pragma unroll
            for (int kk = 0; kk < 4; kk++) {
                float4 w0 = *reinterpret_cast<const float4*>(&sWt[(k4 + kk) * SI + c0]);
                float4 w1 = *reinterpret_cast<const float4*>(&sWt[(k4 + kk) * SI + c0 + 4]);
#pragma unroll
                for (int i = 0; i < 8; i++) {
                    float av = (kk == 0) ? a[i].x : (kk == 1) ? a[i].y : (kk == 2) ? a[i].z : a[i].w;
                    acc[i][0] += av * w0.x;
                    acc[i][1] += av * w0.y;
                    acc[i][2] += av * w0.z;
                    acc[i][3] += av * w0.w;
                    acc[i][4] += av * w1.x;
                    acc[i][5] += av * w1.y;
                    acc[i][6] += av * w1.z;
                    acc[i][7] += av * w1.w;
                }
            }
        }
        __syncthreads();
    }

    float4 b0 = *reinterpret_cast<const float4*>(&bias[c0]);
    float4 b1 = *reinterpret_cast<const float4*>(&bias[c0 + 4]);
#pragma unroll
    for (int i = 0; i < 8; i++) {
        int grow = row0 + r0 + i;
        if (grow >= nrows) break;
        float4 o0, o1;
        o0.x = fmaxf(acc[i][0] + b0.x, 0.f);
        o0.y = fmaxf(acc[i][1] + b0.y, 0.f);
        o0.z = fmaxf(acc[i][2] + b0.z, 0.f);
        o0.w = fmaxf(acc[i][3] + b0.w, 0.f);
        o1.x = fmaxf(acc[i][4] + b1.x, 0.f);
        o1.y = fmaxf(acc[i][5] + b1.y, 0.f);
        o1.z = fmaxf(acc[i][6] + b1.z, 0.f);
        o1.w = fmaxf(acc[i][7] + b1.w, 0.f);
        *reinterpret_cast<float4*>(&out[(long long)grow * D + c0])     = o0;
        *reinterpret_cast<float4*>(&out[(long long)grow * D + c0 + 4]) = o1;
    }
}

// ---------------- fused pool + head (batch is sorted) -----------------------
__device__ __forceinline__ int lower_bound_idx(const void* a, int n, int v) {
    int lo = 0, hi = n;
    while (lo < hi) {
        int mid = (lo + hi) >> 1;
        int av = g_is64 ? (int)((const long long*)a)[mid] : ((const int*)a)[mid];
        if (av < v) lo = mid + 1; else hi = mid;
    }
    return lo;
}

__global__ void pool_head_kernel(const float* __restrict__ h,
                                 const void* __restrict__ batch,
                                 const float* __restrict__ Wlin,
                                 const float* __restrict__ blin,
                                 float* __restrict__ out) {
    __shared__ float sp[D];
    int g = blockIdx.x;
    int t = threadIdx.x;          // 128 threads, one per feature
    int start = lower_bound_idx(batch, N_NODES, g);
    int end   = lower_bound_idx(batch, N_NODES, g + 1);

    float acc = 0.0f;
    for (int i = start; i < end; i++)
        acc += h[(long long)i * D + t];
    float inv = 1.0f / fmaxf((float)(end - start), 1.0f);
    sp[t] = acc * inv;
    __syncthreads();

    int w = t >> 5, lane = t & 31;   // warp w handles class w (4 warps, 4 classes)
    float v = sp[lane]      * Wlin[w * D + lane]
            + sp[lane + 32] * Wlin[w * D + lane + 32]
            + sp[lane + 64] * Wlin[w * D + lane + 64]
            + sp[lane + 96] * Wlin[w * D + lane + 96];
#pragma unroll
    for (int off = 16; off > 0; off >>= 1)
        v += __shfl_down_sync(0xFFFFFFFFu, v, off);
    if (lane == 0) out[g * N_CLASSES + w] = v + blin[w];
}

// ---------------- launch ----------------------------------------------------
extern "C" void kernel_launch(void* const* d_in, const int* in_sizes, int n_in,
                              void* d_out, int out_size) {
    // Resolve inputs BY SIZE, not by position (robust to metadata ordering).
    const float *x = 0, *W1l = 0, *b1 = 0, *W1r = 0, *W2l = 0, *b2 = 0,
                *W2r = 0, *Wlin = 0, *blin = 0;
    const void *ei = 0, *batch = 0;
    int nW = 0, nb = 0;
    for (int i = 0; i < n_in; i++) {
        const void* p = d_in[i];
        switch (in_sizes[i]) {
            case N_NODES * D:      x     = (const float*)p; break;  // 12,800,000
            case 2 * N_EDGES:      ei    = p;               break;  //  3,200,000
            case N_NODES:          batch = p;               break;  //    100,000
            case D * D:                                              //     16,384
                if      (nW == 0) W1l = (const float*)p;
                else if (nW == 1) W1r = (const float*)p;
                else if (nW == 2) W2l = (const float*)p;
                else              W2r = (const float*)p;
                nW++; break;
            case D:                                                  //        128
                if (nb == 0) b1 = (const float*)p; else b2 = (const float*)p;
                nb++; break;
            case N_CLASSES * D:    Wlin  = (const float*)p;  break;  //       512
            case N_CLASSES:        blin  = (const float*)p;  break;  //         4
        }
    }
    float* out = (float*)d_out;
    if (!x || !ei || !batch || !W1l || !W1r || !W2l || !W2r || !b1 || !b2 || !Wlin || !blin)
        return;

    float *agg, *h1, *h2;
    int *deg, *incl, *rowptr, *cursor, *csr, *bsum, *boff;
    cudaGetSymbolAddress((void**)&agg,    g_agg);
    cudaGetSymbolAddress((void**)&h1,     g_h1);
    cudaGetSymbolAddress((void**)&h2,     g_h2);
    cudaGetSymbolAddress((void**)&deg,    g_deg);
    cudaGetSymbolAddress((void**)&incl,   g_incl);
    cudaGetSymbolAddress((void**)&rowptr, g_rowptr);
    cudaGetSymbolAddress((void**)&cursor, g_cursor);
    cudaGetSymbolAddress((void**)&csr,    g_csr);
    cudaGetSymbolAddress((void**)&bsum,   g_bsum);
    cudaGetSymbolAddress((void**)&boff,   g_boff);

    const int smem = 2 * 128 * SI * sizeof(float);   // 135168 B
    cudaFuncSetAttribute(gemm_fused_kernel, cudaFuncAttributeMaxDynamicSharedMemorySize, smem);

    // ---- dtype detection (int32 vs int64 index tensors) ----
    detect_kernel<<<1, 32>>>(ei);

    // ---- CSR build ----
    zero_int_kernel<<<256, 256>>>(deg, N_NODES);
    deg_kernel<<<1024, 256>>>(ei, deg, N_EDGES);
    scan1_kernel<<<SCAN_NBLK, SCAN_BS>>>(deg, incl, bsum, N_NODES);
    scan2_kernel<<<1, 32>>>(bsum, boff);
    scan3_kernel<<<SCAN_NBLK, SCAN_BS>>>(incl, deg, boff, rowptr, cursor, N_NODES, N_EDGES);
    fill_kernel<<<1024, 256>>>(ei, cursor, csr, N_EDGES);

    const int gath_blocks = (N_NODES * 32 + 255) / 256;
    const int gemm_blocks = (N_NODES + 127) / 128;

    // ---- layer 1 ----
    gather_kernel<<<gath_blocks, 256>>>((const float4*)x, rowptr, csr, (float4*)agg, N_NODES);
    gemm_fused_kernel<<<gemm_blocks, 256, smem>>>(agg, x, W1l, W1r, b1, h1, N_NODES);

    // ---- layer 2 ----
    gather_kernel<<<gath_blocks, 256>>>((const float4*)h1, rowptr, csr, (float4*)agg, N_NODES);
    gemm_fused_kernel<<<gemm_blocks, 256, smem>>>(agg, h1, W2l, W2r, b2, h2, N_NODES);

    // ---- pool + head ----
    pool_head_kernel<<<N_GRAPHS, 128>>>(h2, batch, Wlin, blin, out);
}

// round 6
// speedup vs baseline: 1.3543x; 1.3543x over previous
#include <cuda_runtime.h>
#include <cuda_bf16.h>
#include <cstdint>

#define N_NODES   100000
#define N_EDGES   1600000
#define D         128
#define N_GRAPHS  512
#define N_CLASSES 4
#define SCAN_BS   1024
#define SCAN_NBLK ((N_NODES + SCAN_BS - 1) / SCAN_BS)   // 98

// ---------------- scratch (device globals; 16B aligned for LDG/STG.128) ----
__device__ __align__(16) float g_agg[N_NODES * D];
__device__ __align__(16) float g_h1 [N_NODES * D];
__device__ __align__(16) float g_h2 [N_NODES * D];
__device__ int g_deg   [N_NODES];
__device__ int g_incl  [N_NODES];
__device__ int g_rowptr[N_NODES + 1];
__device__ int g_cursor[N_NODES];
__device__ int g_csr   [N_EDGES];
__device__ int g_bsum  [SCAN_NBLK];
__device__ int g_boff  [SCAN_NBLK];
__device__ int g_is64;   // 1 if index tensors are int64, 0 if int32

// ---------------- dtype detection ----------------
__global__ void detect_kernel(const void* ei) {
    if (threadIdx.x == 0 && blockIdx.x == 0) {
        const unsigned long long* p = (const unsigned long long*)ei;
        int ok64 = 1;
        for (int i = 0; i < 16; i++)
            if (p[i] >= (unsigned long long)N_NODES) { ok64 = 0; break; }
        g_is64 = ok64;
    }
}

__device__ __forceinline__ int load_idx(const void* base, long long i) {
    return g_is64 ? (int)((const long long*)base)[i]
                  : ((const int*)base)[i];
}

// ---------------- CSR build ----------------
__global__ void zero_int_kernel(int* __restrict__ p, int n) {
    int i = blockIdx.x * blockDim.x + threadIdx.x;
    int stride = gridDim.x * blockDim.x;
    for (; i < n; i += stride) p[i] = 0;
}

__global__ void deg_kernel(const void* __restrict__ ei, int* __restrict__ deg, int ne) {
    int i = blockIdx.x * blockDim.x + threadIdx.x;
    int stride = gridDim.x * blockDim.x;
    for (; i < ne; i += stride) {
        int d = load_idx(ei, (long long)N_EDGES + i);
        if ((unsigned)d < (unsigned)N_NODES)
            atomicAdd(&deg[d], 1);
    }
}

__global__ void scan1_kernel(const int* __restrict__ deg, int* __restrict__ incl,
                             int* __restrict__ bsum, int n) {
    __shared__ int s[SCAN_BS];
    int i = blockIdx.x * SCAN_BS + threadIdx.x;
    int v = (i < n) ? deg[i] : 0;
    s[threadIdx.x] = v;
    __syncthreads();
    for (int off = 1; off < SCAN_BS; off <<= 1) {
        int t = (threadIdx.x >= off) ? s[threadIdx.x - off] : 0;
        __syncthreads();
        s[threadIdx.x] += t;
        __syncthreads();
    }
    if (i < n) incl[i] = s[threadIdx.x];
    if (threadIdx.x == SCAN_BS - 1) bsum[blockIdx.x] = s[SCAN_BS - 1];
}

__global__ void scan2_kernel(const int* __restrict__ bsum, int* __restrict__ boff) {
    if (threadIdx.x == 0) {
        int running = 0;
        for (int b = 0; b < SCAN_NBLK; b++) { boff[b] = running; running += bsum[b]; }
    }
}

__global__ void scan3_kernel(const int* __restrict__ incl, const int* __restrict__ deg,
                             const int* __restrict__ boff, int* __restrict__ rowptr,
                             int* __restrict__ cursor, int n, int total) {
    int i = blockIdx.x * SCAN_BS + threadIdx.x;
    if (i < n) {
        int ex = incl[i] - deg[i] + boff[blockIdx.x];
        rowptr[i] = ex;
        cursor[i] = ex;
        if (i == n - 1) rowptr[n] = total;
    }
}

__global__ void fill_kernel(const void* __restrict__ ei,
                            int* __restrict__ cursor, int* __restrict__ csr, int ne) {
    int i = blockIdx.x * blockDim.x + threadIdx.x;
    int stride = gridDim.x * blockDim.x;
    for (; i < ne; i += stride) {
        int s = load_idx(ei, i);
        int d = load_idx(ei, (long long)N_EDGES + i);
        if ((unsigned)d < (unsigned)N_NODES && (unsigned)s < (unsigned)N_NODES) {
            int pos = atomicAdd(&cursor[d], 1);
            if ((unsigned)pos < (unsigned)N_EDGES) csr[pos] = s;
        }
    }
}

// ---------------- gather aggregate: agg[n] = mean_{e: dst=n} feat[src_e] ----
__global__ void gather_kernel(const float4* __restrict__ feat4,
                              const int* __restrict__ rowptr,
                              const int* __restrict__ csr,
                              float4* __restrict__ agg4, int n) {
    int w    = (blockIdx.x * blockDim.x + threadIdx.x) >> 5;
    int lane = threadIdx.x & 31;
    if (w >= n) return;
    int beg = rowptr[w], end = rowptr[w + 1];
    float4 acc = make_float4(0.f, 0.f, 0.f, 0.f);
    for (int e = beg; e < end; e++) {
        int s = __ldg(&csr[e]);
        float4 v = feat4[(long long)s * 32 + lane];
        acc.x += v.x; acc.y += v.y; acc.z += v.z; acc.w += v.w;
    }
    float inv = 1.0f / fmaxf((float)(end - beg), 1.0f);
    acc.x *= inv; acc.y *= inv; acc.z *= inv; acc.w *= inv;
    agg4[(long long)w * 32 + lane] = acc;
}

// ---------------- tf32 tensor-core fused SAGE layer GEMM -------------------
// out[r,:] = relu( agg[r,:] @ Wl^T + x[r,:] @ Wr^T + b )
// Block: 128 rows x 128 cols, 8 warps in 4x2 grid; warp = 32 rows x 64 cols
// = 2 (m16) x 8 (n8) mma tiles, k stepped by 8 (tf32 m16n8k8).
// .row.col mma: A row-major [m][k], B col-major = W's natural [n][k] layout.
#define SI2 132   // padded smem stride in words

__device__ __forceinline__ uint32_t f2tf32(float f) {
    uint32_t r;
    asm("cvt.rna.tf32.f32 %0, %1;" : "=r"(r) : "f"(f));
    return r;
}

__device__ __forceinline__ void mma_tf32(float c[4], const uint32_t a[4], const uint32_t b[2]) {
    asm volatile(
        "mma.sync.aligned.m16n8k8.row.col.f32.tf32.tf32.f32 "
        "{%0,%1,%2,%3}, {%4,%5,%6,%7}, {%8,%9}, {%0,%1,%2,%3};"
        : "+f"(c[0]), "+f"(c[1]), "+f"(c[2]), "+f"(c[3])
        : "r"(a[0]), "r"(a[1]), "r"(a[2]), "r"(a[3]), "r"(b[0]), "r"(b[1]));
}

__global__ __launch_bounds__(256)
void gemm_fused_kernel(const float* __restrict__ agg,
                       const float* __restrict__ xin,
                       const float* __restrict__ Wl,
                       const float* __restrict__ Wr,
                       const float* __restrict__ bias,
                       float* __restrict__ out, int nrows) {
    extern __shared__ uint32_t sm[];
    uint32_t* sIn = sm;              // [128][SI2]  input rows (tf32)
    uint32_t* sW  = sm + 128 * SI2;  // [128][SI2]  weights natural [c][k] (tf32)

    const int tid   = threadIdx.x;
    const int wid   = tid >> 5;
    const int lane  = tid & 31;
    const int g     = lane >> 2;     // groupID
    const int t     = lane & 3;      // threadID_in_group
    const int row0  = blockIdx.x * 128;
    const int rbase = (wid >> 1) * 32;   // warp row base within tile
    const int cbase = (wid & 1) * 64;    // warp col base within tile

    float acc[2][8][4];
#pragma unroll
    for (int mi = 0; mi < 2; mi++)
#pragma unroll
        for (int ni = 0; ni < 8; ni++)
#pragma unroll
            for (int j = 0; j < 4; j++) acc[mi][ni][j] = 0.0f;

#pragma unroll 1
    for (int chunk = 0; chunk < 2; ++chunk) {
        const float* In = chunk ? xin : agg;
        const float* W  = chunk ? Wr  : Wl;

        // stage input tile [128][128] (tf32)
        for (int idx = tid; idx < 128 * (D / 4); idx += 256) {
            int r  = idx >> 5;
            int k4 = (idx & 31) * 4;
            int grow = row0 + r;
            uint4 u = make_uint4(0u, 0u, 0u, 0u);
            if (grow < nrows) {
                float4 v = *reinterpret_cast<const float4*>(&In[(long long)grow * D + k4]);
                u.x = f2tf32(v.x); u.y = f2tf32(v.y); u.z = f2tf32(v.z); u.w = f2tf32(v.w);
            }
            *reinterpret_cast<uint4*>(&sIn[r * SI2 + k4]) = u;
        }
        // stage weights natural layout [c][k] (tf32)
        for (int idx = tid; idx < 128 * (D / 4); idx += 256) {
            int c  = idx >> 5;
            int k4 = (idx & 31) * 4;
            float4 v = *reinterpret_cast<const float4*>(&W[(long long)c * D + k4]);
            uint4 u;
            u.x = f2tf32(v.x); u.y = f2tf32(v.y); u.z = f2tf32(v.z); u.w = f2tf32(v.w);
            *reinterpret_cast<uint4*>(&sW[c * SI2 + k4]) = u;
        }
        __syncthreads();

#pragma unroll
        for (int k0 = 0; k0 < D; k0 += 8) {
            uint32_t a[2][4];
#pragma unroll
            for (int mi = 0; mi < 2; mi++) {
                int r = rbase + mi * 16 + g;
                a[mi][0] = sIn[r * SI2 + k0 + t];
                a[mi][1] = sIn[(r + 8) * SI2 + k0 + t];
                a[mi][2] = sIn[r * SI2 + k0 + t + 4];
                a[mi][3] = sIn[(r + 8) * SI2 + k0 + t + 4];
            }
            uint32_t b[8][2];
#pragma unroll
            for (int ni = 0; ni < 8; ni++) {
                int c = cbase + ni * 8 + g;
                b[ni][0] = sW[c * SI2 + k0 + t];
                b[ni][1] = sW[c * SI2 + k0 + t + 4];
            }
#pragma unroll
            for (int mi = 0; mi < 2; mi++)
#pragma unroll
                for (int ni = 0; ni < 8; ni++)
                    mma_tf32(acc[mi][ni], a[mi], b[ni]);
        }
        __syncthreads();
    }

    // epilogue: bias + relu, write float2 pairs
#pragma unroll
    for (int ni = 0; ni < 8; ni++) {
        int cn = cbase + ni * 8 + 2 * t;
        float bx = __ldg(&bias[cn]);
        float by = __ldg(&bias[cn + 1]);
#pragma unroll
        for (int mi = 0; mi < 2; mi++) {
            int r_lo = row0 + rbase + mi * 16 + g;
            int r_hi = r_lo + 8;
            if (r_lo < nrows) {
                float2 o;
                o.x = fmaxf(acc[mi][ni][0] + bx, 0.f);
                o.y = fmaxf(acc[mi][ni][1] + by, 0.f);
                *reinterpret_cast<float2*>(&out[(long long)r_lo * D + cn]) = o;
            }
            if (r_hi < nrows) {
                float2 o;
                o.x = fmaxf(acc[mi][ni][2] + bx, 0.f);
                o.y = fmaxf(acc[mi][ni][3] + by, 0.f);
                *reinterpret_cast<float2*>(&out[(long long)r_hi * D + cn]) = o;
            }
        }
    }
}

// ---------------- fused pool + head (batch is sorted) -----------------------
__device__ __forceinline__ int lower_bound_idx(const void* a, int n, int v) {
    int lo = 0, hi = n;
    while (lo < hi) {
        int mid = (lo + hi) >> 1;
        int av = g_is64 ? (int)((const long long*)a)[mid] : ((const int*)a)[mid];
        if (av < v) lo = mid + 1; else hi = mid;
    }
    return lo;
}

__global__ void pool_head_kernel(const float* __restrict__ h,
                                 const void* __restrict__ batch,
                                 const float* __restrict__ Wlin,
                                 const float* __restrict__ blin,
                                 float* __restrict__ out) {
    __shared__ float sp[D];
    int g = blockIdx.x;
    int t = threadIdx.x;
    int start = lower_bound_idx(batch, N_NODES, g);
    int end   = lower_bound_idx(batch, N_NODES, g + 1);

    float acc = 0.0f;
    for (int i = start; i < end; i++)
        acc += h[(long long)i * D + t];
    float inv = 1.0f / fmaxf((float)(end - start), 1.0f);
    sp[t] = acc * inv;
    __syncthreads();

    int w = t >> 5, lane = t & 31;
    float v = sp[lane]      * Wlin[w * D + lane]
            + sp[lane + 32] * Wlin[w * D + lane + 32]
            + sp[lane + 64] * Wlin[w * D + lane + 64]
            + sp[lane + 96] * Wlin[w * D + lane + 96];
#pragma unroll
    for (int off = 16; off > 0; off >>= 1)
        v += __shfl_down_sync(0xFFFFFFFFu, v, off);
    if (lane == 0) out[g * N_CLASSES + w] = v + blin[w];
}

// ---------------- launch ----------------------------------------------------
extern "C" void kernel_launch(void* const* d_in, const int* in_sizes, int n_in,
                              void* d_out, int out_size) {
    const float *x = 0, *W1l = 0, *b1 = 0, *W1r = 0, *W2l = 0, *b2 = 0,
                *W2r = 0, *Wlin = 0, *blin = 0;
    const void *ei = 0, *batch = 0;
    int nW = 0, nb = 0;
    for (int i = 0; i < n_in; i++) {
        const void* p = d_in[i];
        switch (in_sizes[i]) {
            case N_NODES * D:      x     = (const float*)p; break;
            case 2 * N_EDGES:      ei    = p;               break;
            case N_NODES:          batch = p;               break;
            case D * D:
                if      (nW == 0) W1l = (const float*)p;
                else if (nW == 1) W1r = (const float*)p;
                else if (nW == 2) W2l = (const float*)p;
                else              W2r = (const float*)p;
                nW++; break;
            case D:
                if (nb == 0) b1 = (const float*)p; else b2 = (const float*)p;
                nb++; break;
            case N_CLASSES * D:    Wlin  = (const float*)p;  break;
            case N_CLASSES:        blin  = (const float*)p;  break;
        }
    }
    float* out = (float*)d_out;
    if (!x || !ei || !batch || !W1l || !W1r || !W2l || !W2r || !b1 || !b2 || !Wlin || !blin)
        return;

    float *agg, *h1, *h2;
    int *deg, *incl, *rowptr, *cursor, *csr, *bsum, *boff;
    cudaGetSymbolAddress((void**)&agg,    g_agg);
    cudaGetSymbolAddress((void**)&h1,     g_h1);
    cudaGetSymbolAddress((void**)&h2,     g_h2);
    cudaGetSymbolAddress((void**)&deg,    g_deg);
    cudaGetSymbolAddress((void**)&incl,   g_incl);
    cudaGetSymbolAddress((void**)&rowptr, g_rowptr);
    cudaGetSymbolAddress((void**)&cursor, g_cursor);
    cudaGetSymbolAddress((void**)&csr,    g_csr);
    cudaGetSymbolAddress((void**)&bsum,   g_bsum);
    cudaGetSymbolAddress((void**)&boff,   g_boff);

    const int smem = 2 * 128 * SI2 * sizeof(uint32_t);   // 135168 B
    cudaFuncSetAttribute(gemm_fused_kernel, cudaFuncAttributeMaxDynamicSharedMemorySize, smem);

    detect_kernel<<<1, 32>>>(ei);

    // ---- CSR build ----
    zero_int_kernel<<<256, 256>>>(deg, N_NODES);
    deg_kernel<<<1024, 256>>>(ei, deg, N_EDGES);
    scan1_kernel<<<SCAN_NBLK, SCAN_BS>>>(deg, incl, bsum, N_NODES);
    scan2_kernel<<<1, 32>>>(bsum, boff);
    scan3_kernel<<<SCAN_NBLK, SCAN_BS>>>(incl, deg, boff, rowptr, cursor, N_NODES, N_EDGES);
    fill_kernel<<<1024, 256>>>(ei, cursor, csr, N_EDGES);

    const int gath_blocks = (N_NODES * 32 + 255) / 256;
    const int gemm_blocks = (N_NODES + 127) / 128;

    // ---- layer 1 ----
    gather_kernel<<<gath_blocks, 256>>>((const float4*)x, rowptr, csr, (float4*)agg, N_NODES);
    gemm_fused_kernel<<<gemm_blocks, 256, smem>>>(agg, x, W1l, W1r, b1, h1, N_NODES);

    // ---- layer 2 ----
    gather_kernel<<<gath_blocks, 256>>>((const float4*)h1, rowptr, csr, (float4*)agg, N_NODES);
    gemm_fused_kernel<<<gemm_blocks, 256, smem>>>(agg, h1, W2l, W2r, b2, h2, N_NODES);

    // ---- pool + head ----
    pool_head_kernel<<<N_GRAPHS, 128>>>(h2, batch, Wlin, blin, out);
}